// round 17
// baseline (speedup 1.0000x reference)
#include <cuda_runtime.h>
#include <cuda_fp16.h>
#include <math.h>
#include <stdint.h>

// Problem dims
#define N_TOK 4096
#define C_DIM 512
#define NH 8
#define DH 64
#define L2E 1.44269504f

// ---------------- scratch (device globals, no runtime alloc) ----------------
__device__ float  g_dist[(size_t)N_TOK * N_TOK];   // 64 MB haversine distances
__device__ __half g_xh[N_TOK * C_DIM];             // X in fp16
__device__ __half g_wqh[3 * C_DIM * C_DIM];        // w_qkv in fp16
__device__ __half g_woh[C_DIM * C_DIM];            // w_out in fp16
__device__ __half g_q[NH * N_TOK * DH];            // head-major [h][n][d], q scaled by L2E/8
__device__ __half g_k[NH * N_TOK * DH];
__device__ __half g_v[NH * N_TOK * DH];
__device__ __half g_o[NH * N_TOK * DH];            // attention output (fp16)
__device__ float4 g_trigA[N_TOK];                  // {sin(lat/2), cos(lat/2), sin(lon/2), cos(lon/2)}
__device__ float  g_clat[N_TOK];                   // cos(lat)
__device__ double g_sum;
__device__ double g_sumsq;
__device__ float  g_neg_inv_std;                   // includes L2E factor

// ---------------- helpers ----------------
__device__ __forceinline__ void mma16(float c[4], const uint32_t a[4], uint32_t b0, uint32_t b1) {
    asm volatile(
        "mma.sync.aligned.m16n8k16.row.col.f32.f16.f16.f32 "
        "{%0,%1,%2,%3}, {%4,%5,%6,%7}, {%8,%9}, {%0,%1,%2,%3};"
        : "+f"(c[0]), "+f"(c[1]), "+f"(c[2]), "+f"(c[3])
        : "r"(a[0]), "r"(a[1]), "r"(a[2]), "r"(a[3]), "r"(b0), "r"(b1));
}
__device__ __forceinline__ void ldsm4(uint32_t r[4], uint32_t addr) {
    asm volatile("ldmatrix.sync.aligned.m8n8.x4.shared.b16 {%0,%1,%2,%3}, [%4];"
        : "=r"(r[0]), "=r"(r[1]), "=r"(r[2]), "=r"(r[3]) : "r"(addr));
}
__device__ __forceinline__ void ldsm4t(uint32_t r[4], uint32_t addr) {
    asm volatile("ldmatrix.sync.aligned.m8n8.x4.trans.shared.b16 {%0,%1,%2,%3}, [%4];"
        : "=r"(r[0]), "=r"(r[1]), "=r"(r[2]), "=r"(r[3]) : "r"(addr));
}
__device__ __forceinline__ uint32_t smem_u32(const void* p) {
    uint32_t a;
    asm("{ .reg .u64 t; cvta.to.shared.u64 t, %1; cvt.u32.u64 %0, t; }" : "=r"(a) : "l"(p));
    return a;
}
__device__ __forceinline__ void cpa16(uint32_t s, const void* g) {
    asm volatile("cp.async.cg.shared.global [%0], [%1], 16;" :: "r"(s), "l"(g));
}
#define CP_COMMIT() asm volatile("cp.async.commit_group;" ::: "memory")
#define CP_WAIT(n)  asm volatile("cp.async.wait_group %0;" :: "n"(n) : "memory")

__device__ __forceinline__ uint32_t packh2(float a, float b) {
    __half2 h = __floats2half2_rn(a, b);
    return *(uint32_t*)&h;
}
__device__ __forceinline__ float ex2(float x) {
    float y;
    asm("ex2.approx.ftz.f32 %0, %1;" : "=f"(y) : "f"(x));
    return y;
}

// ---------------- kernel 0b: fp16 conversion of X, w_qkv, w_out ----------------
__global__ void cvt_kernel(const float* __restrict__ x,
                           const float* __restrict__ wq,
                           const float* __restrict__ wo) {
    int idx = blockIdx.x * 256 + threadIdx.x;
    const float4* src;
    uint2* dst;
    if (idx < 524288) {
        src = (const float4*)x + idx;
        dst = (uint2*)g_xh + idx;
    } else if (idx < 524288 + 196608) {
        src = (const float4*)wq + (idx - 524288);
        dst = (uint2*)g_wqh + (idx - 524288);
    } else {
        src = (const float4*)wo + (idx - 720896);
        dst = (uint2*)g_woh + (idx - 720896);
    }
    float4 v = *src;
    uint2 o;
    o.x = packh2(v.x, v.y);
    o.y = packh2(v.z, v.w);
    *dst = o;
}

// ---------------- kernel 0c: trig precompute (+ accumulator init) ----------------
__global__ void trig_kernel(const float* __restrict__ lat, const float* __restrict__ lon) {
    if (blockIdx.x == 0 && threadIdx.x == 0) {
        g_sum = 0.0;
        g_sumsq = 0.0;
    }
    int j = blockIdx.x * 256 + threadIdx.x;
    float la = lat[j], lo = lon[j];
    float sh, ch, so, co;
    __sincosf(la * 0.5f, &sh, &ch);
    __sincosf(lo * 0.5f, &so, &co);
    g_trigA[j] = make_float4(sh, ch, so, co);
    g_clat[j] = __cosf(la);
}

// ---------------- kernel 1: symmetric haversine distance (upper-tri tiles) ----------------
#define NTILE 64
__global__ void dist_kernel2() {
    __shared__ float tile[64][65];
    __shared__ float4 tI[64];
    __shared__ float  cI[64];
    __shared__ float4 tJ[64];
    __shared__ float  cJ[64];
    __shared__ double shs[256];
    __shared__ double shs2[256];

    int p = blockIdx.x;
    int bi = (int)((129.0f - sqrtf(16641.0f - 8.0f * (float)p)) * 0.5f);
    if (bi < 0) bi = 0;
    if (bi > 63) bi = 63;
    while (bi > 0 && bi * 64 - bi * (bi - 1) / 2 > p) bi--;
    while (bi < 63 && (bi + 1) * 64 - (bi + 1) * bi / 2 <= p) bi++;
    int bj = bi + (p - (bi * 64 - bi * (bi - 1) / 2));
    int i0 = bi * 64, j0 = bj * 64;

    int tid = threadIdx.x;
    if (tid < 64) {
        tI[tid] = g_trigA[i0 + tid];
        cI[tid] = g_clat[i0 + tid];
    } else if (tid < 128) {
        int t = tid - 64;
        tJ[t] = g_trigA[j0 + t];
        cJ[t] = g_clat[j0 + t];
    }
    __syncthreads();

    int c4 = (tid & 15) * 4;
    int r0 = tid >> 4;
    double s = 0.0, s2 = 0.0;

#pragma unroll
    for (int rr = 0; rr < 4; rr++) {
        int row = r0 + rr * 16;
        float4 ti = tI[row];
        float cli = cI[row];
        float4 v;
        float dv[4];
#pragma unroll
        for (int cc = 0; cc < 4; cc++) {
            int col = c4 + cc;
            float4 tj = tJ[col];
            float clj = cJ[col];
            float sdlat = ti.x * tj.y - ti.y * tj.x;
            float sdlon = ti.z * tj.w - ti.w * tj.z;
            float a = sdlat * sdlat + cli * clj * (sdlon * sdlon);
            a = fminf(fmaxf(a, 0.0f), 1.0f);
            float d = 2.0f * asinf(sqrtf(a));
            dv[cc] = d;
            tile[row][col] = d;
            s += (double)d;
            s2 += (double)d * (double)d;
        }
        v.x = dv[0]; v.y = dv[1]; v.z = dv[2]; v.w = dv[3];
        *(float4*)&g_dist[(size_t)(i0 + row) * N_TOK + j0 + c4] = v;
    }

    if (bi != bj) { s *= 2.0; s2 *= 2.0; }
    shs[tid] = s;
    shs2[tid] = s2;
    __syncthreads();

    if (bi != bj) {
#pragma unroll
        for (int rr = 0; rr < 4; rr++) {
            int row = r0 + rr * 16;
            float4 v;
            v.x = tile[c4 + 0][row];
            v.y = tile[c4 + 1][row];
            v.z = tile[c4 + 2][row];
            v.w = tile[c4 + 3][row];
            *(float4*)&g_dist[(size_t)(j0 + row) * N_TOK + i0 + c4] = v;
        }
    }

    for (int off = 128; off > 0; off >>= 1) {
        if (tid < off) {
            shs[tid] += shs[tid + off];
            shs2[tid] += shs2[tid + off];
        }
        __syncthreads();
    }
    if (tid == 0) {
        atomicAdd(&g_sum, shs[0]);
        atomicAdd(&g_sumsq, shs2[0]);
    }
}

// ---------------- kernel 2: finalize std (ddof=1), fold log2e ----------------
__global__ void finalize_kernel() {
    double M = (double)N_TOK * (double)N_TOK;
    double mean = g_sum / M;
    double var = (g_sumsq - g_sum * mean) / (M - 1.0);
    g_neg_inv_std = (float)(-(double)L2E / sqrt(var));
}

// ====== fp16 GEMM tile geometry (shared by qkv/out projections) ======
#define ROWB 144
#define PA0_B 0
#define PA1_B 18432
#define PB0_B 36864
#define PB1_B 46080
#define PROJ_SMEM_BYTES 55296

// ---------------- kernel 3: QKV projection (fp16 mma) ----------------
__global__ void __launch_bounds__(256, 2) qkv_gemm_h(const float* __restrict__ bq) {
    extern __shared__ char smem[];
    uint32_t sbase = smem_u32(smem);
    int j0 = blockIdx.x * 64;
    int i0 = blockIdx.y * 128;
    int tid = threadIdx.x;
    int warp = tid >> 5;
    int lane = tid & 31;
    int gid = lane >> 2;
    int tig = lane & 3;
    int w16 = warp * 16;
    int l15 = lane & 15;
    int lhi = (lane >> 4) * 16;
    int l7 = lane & 7;
    int r16 = (lane & 16) ? 8 : 0;
    int b8 = (lane & 8) ? 16 : 0;

    const __half* Ag = g_xh + (size_t)i0 * C_DIM;
    const __half* Bg = g_wqh + (size_t)j0 * C_DIM;

#pragma unroll
    for (int t = 0; t < 4; t++) {
        int id = tid + t * 256;
        int r = id >> 3, c = id & 7;
        cpa16(sbase + PA0_B + r * ROWB + c * 16, Ag + (size_t)r * C_DIM + c * 8);
    }
#pragma unroll
    for (int t = 0; t < 2; t++) {
        int id = tid + t * 256;
        int r = id >> 3, c = id & 7;
        cpa16(sbase + PB0_B + r * ROWB + c * 16, Bg + (size_t)r * C_DIM + c * 8);
    }
    CP_COMMIT();

    float acc[8][4];
#pragma unroll
    for (int n = 0; n < 8; n++)
#pragma unroll
        for (int q = 0; q < 4; q++) acc[n][q] = 0.0f;

    for (int kc = 0; kc < 8; kc++) {
        int cur = kc & 1;
        uint32_t Ac = sbase + (cur ? PA1_B : PA0_B);
        uint32_t Bc = sbase + (cur ? PB1_B : PB0_B);
        __syncthreads();
        if (kc + 1 < 8) {
            uint32_t An = sbase + (cur ? PA0_B : PA1_B);
            uint32_t Bn = sbase + (cur ? PB0_B : PB1_B);
            int ko = (kc + 1) * 64;
#pragma unroll
            for (int t = 0; t < 4; t++) {
                int id = tid + t * 256;
                int r = id >> 3, c = id & 7;
                cpa16(An + r * ROWB + c * 16, Ag + (size_t)r * C_DIM + ko + c * 8);
            }
#pragma unroll
            for (int t = 0; t < 2; t++) {
                int id = tid + t * 256;
                int r = id >> 3, c = id & 7;
                cpa16(Bn + r * ROWB + c * 16, Bg + (size_t)r * C_DIM + ko + c * 8);
            }
            CP_COMMIT();
            CP_WAIT(1);
        } else {
            CP_WAIT(0);
        }
        __syncthreads();

#pragma unroll
        for (int k = 0; k < 4; k++) {
            uint32_t a[4];
            ldsm4(a, Ac + (w16 + l15) * ROWB + k * 32 + lhi);
#pragma unroll
            for (int np = 0; np < 4; np++) {
                uint32_t b[4];
                ldsm4(b, Bc + (np * 16 + r16 + l7) * ROWB + k * 32 + b8);
                mma16(acc[2 * np], a, b[0], b[1]);
                mma16(acc[2 * np + 1], a, b[2], b[3]);
            }
        }
    }

    int part = j0 / C_DIM;
    int h = (j0 % C_DIM) / DH;
    __half* dst = (part == 0) ? g_q : ((part == 1) ? g_k : g_v);
    float sc = (part == 0) ? (0.125f * L2E) : 1.0f;
    dst += (size_t)h * N_TOK * DH;
#pragma unroll
    for (int n = 0; n < 8; n++) {
        int col = n * 8 + 2 * tig;
        float2 bb = *(const float2*)&bq[j0 + col];
        int r0 = i0 + w16 + gid;
        *(uint32_t*)&dst[(size_t)r0 * DH + col] =
            packh2((acc[n][0] + bb.x) * sc, (acc[n][1] + bb.y) * sc);
        *(uint32_t*)&dst[(size_t)(r0 + 8) * DH + col] =
            packh2((acc[n][2] + bb.x) * sc, (acc[n][3] + bb.y) * sc);
    }
}

// ---------------- kernel 4: flash attention (fp16 mma, exp2, NO max tracking) ----------------
// Logits are analytically bounded (|z| < ~10 << ex2 range), so softmax shift m=0 is
// numerically safe: p = ex2(z), out = sum(p*V)/sum(p). Removes max/shfl/rescale machinery.
#define QS_B 0
#define K0_B 18432
#define V0_B (18432 + 9216)
#define K1_B (18432 + 2 * 9216)
#define V1_B (18432 + 3 * 9216)
#define ATTN_SMEM_BYTES (18432 + 4 * 9216)

__global__ void __launch_bounds__(256, 2) attn_mma() {
    extern __shared__ char smem[];
    uint32_t sbase = smem_u32(smem);

    int tid = threadIdx.x;
    int warp = tid >> 5;
    int lane = tid & 31;
    int gid = lane >> 2;
    int tig = lane & 3;
    int w16 = warp * 16;
    int h = blockIdx.y;
    int i0 = blockIdx.x * 128;
    float nis = g_neg_inv_std;

    const __half* Qg = g_q + (size_t)h * N_TOK * DH + (size_t)i0 * DH;
    const __half* Kg = g_k + (size_t)h * N_TOK * DH;
    const __half* Vg = g_v + (size_t)h * N_TOK * DH;

    int l15 = lane & 15;
    int lhi = (lane >> 4) * 16;
    int l7 = lane & 7;
    int r16 = (lane & 16) ? 8 : 0;
    int b8 = (lane & 8) ? 16 : 0;

#pragma unroll
    for (int t = 0; t < 4; t++) {
        int id = tid + t * 256;
        int r = id >> 3, c = id & 7;
        cpa16(sbase + QS_B + r * ROWB + c * 16, Qg + r * DH + c * 8);
    }
#pragma unroll
    for (int t = 0; t < 2; t++) {
        int id = tid + t * 256;
        int r = id >> 3, c = id & 7;
        cpa16(sbase + K0_B + r * ROWB + c * 16, Kg + r * DH + c * 8);
        cpa16(sbase + V0_B + r * ROWB + c * 16, Vg + r * DH + c * 8);
    }
    CP_COMMIT();

    float l0 = 0.0f, l1 = 0.0f;
    float o[8][4];
#pragma unroll
    for (int n = 0; n < 8; n++)
#pragma unroll
        for (int q = 0; q < 4; q++) o[n][q] = 0.0f;

    const float* d0base = g_dist + (size_t)(i0 + w16 + gid) * N_TOK + 2 * tig;
    const float* d1base = d0base + (size_t)8 * N_TOK;

    for (int kb = 0; kb < N_TOK / 64; kb++) {
        int j0 = kb * 64;
        int cur = kb & 1;
        uint32_t Kc = sbase + (cur ? K1_B : K0_B);
        uint32_t Vc = sbase + (cur ? V1_B : V0_B);

        // bias loads early — latency covered by staging + S-MMA
        float2 bx0[8], bx1[8];
#pragma unroll
        for (int n = 0; n < 8; n++) {
            bx0[n] = *(const float2*)(d0base + j0 + n * 8);
            bx1[n] = *(const float2*)(d1base + j0 + n * 8);
        }

        __syncthreads();
        if (kb + 1 < N_TOK / 64) {
            uint32_t Kn = sbase + (cur ? K0_B : K1_B);
            uint32_t Vn = sbase + (cur ? V0_B : V1_B);
            const __half* Kgn = Kg + (size_t)(j0 + 64) * DH;
            const __half* Vgn = Vg + (size_t)(j0 + 64) * DH;
#pragma unroll
            for (int t = 0; t < 2; t++) {
                int id = tid + t * 256;
                int r = id >> 3, c = id & 7;
                cpa16(Kn + r * ROWB + c * 16, Kgn + r * DH + c * 8);
                cpa16(Vn + r * ROWB + c * 16, Vgn + r * DH + c * 8);
            }
            CP_COMMIT();
            CP_WAIT(1);
        } else {
            CP_WAIT(0);
        }
        __syncthreads();

        // S = Q @ K^T (log2-domain logits; q pre-scaled by L2E/8)
        float s[8][4];
#pragma unroll
        for (int n = 0; n < 8; n++)
#pragma unroll
            for (int q = 0; q < 4; q++) s[n][q] = 0.0f;

#pragma unroll
        for (int k = 0; k < 4; k++) {
            uint32_t a[4];
            ldsm4(a, sbase + QS_B + (w16 + l15) * ROWB + k * 32 + lhi);
#pragma unroll
            for (int np = 0; np < 4; np++) {
                uint32_t b[4];
                ldsm4(b, Kc + (np * 16 + r16 + l7) * ROWB + k * 32 + b8);
                mma16(s[2 * np], a, b[0], b[1]);
                mma16(s[2 * np + 1], a, b[2], b[3]);
            }
        }

        // p = ex2(s + bias*nis); accumulate l; pack directly into PV A-frags
        float sum0 = 0.0f, sum1 = 0.0f;
#pragma unroll
        for (int n = 0; n < 8; n++) {
            s[n][0] = ex2(fmaf(bx0[n].x, nis, s[n][0]));
            s[n][1] = ex2(fmaf(bx0[n].y, nis, s[n][1]));
            s[n][2] = ex2(fmaf(bx1[n].x, nis, s[n][2]));
            s[n][3] = ex2(fmaf(bx1[n].y, nis, s[n][3]));
            sum0 += s[n][0] + s[n][1];
            sum1 += s[n][2] + s[n][3];
        }
        l0 += sum0;
        l1 += sum1;

        // O += P @ V (P in registers)
#pragma unroll
        for (int kk = 0; kk < 4; kk++) {
            uint32_t a[4];
            a[0] = packh2(s[2 * kk][0], s[2 * kk][1]);
            a[1] = packh2(s[2 * kk][2], s[2 * kk][3]);
            a[2] = packh2(s[2 * kk + 1][0], s[2 * kk + 1][1]);
            a[3] = packh2(s[2 * kk + 1][2], s[2 * kk + 1][3]);
#pragma unroll
            for (int dp = 0; dp < 4; dp++) {
                uint32_t b[4];
                ldsm4t(b, Vc + (kk * 16 + l15) * ROWB + dp * 32 + lhi);
                mma16(o[2 * dp], a, b[0], b[1]);
                mma16(o[2 * dp + 1], a, b[2], b[3]);
            }
        }
    }

    l0 += __shfl_xor_sync(0xffffffffu, l0, 1);
    l0 += __shfl_xor_sync(0xffffffffu, l0, 2);
    l1 += __shfl_xor_sync(0xffffffffu, l1, 1);
    l1 += __shfl_xor_sync(0xffffffffu, l1, 2);
    float inv0 = 1.0f / l0;
    float inv1 = 1.0f / l1;

    __half* O = g_o + ((size_t)h * N_TOK + i0) * DH;
#pragma unroll
    for (int n = 0; n < 8; n++) {
        int col = n * 8 + 2 * tig;
        *(uint32_t*)&O[(size_t)(w16 + gid) * DH + col] = packh2(o[n][0] * inv0, o[n][1] * inv0);
        *(uint32_t*)&O[(size_t)(w16 + gid + 8) * DH + col] = packh2(o[n][2] * inv1, o[n][3] * inv1);
    }
}

// ---------------- kernel 5: output projection (fp16 mma) ----------------
__global__ void __launch_bounds__(256, 2) out_gemm_h(const float* __restrict__ bo,
                                                     float* __restrict__ out) {
    extern __shared__ char smem[];
    uint32_t sbase = smem_u32(smem);
    int j0 = blockIdx.x * 64;
    int i0 = blockIdx.y * 128;
    int tid = threadIdx.x;
    int warp = tid >> 5;
    int lane = tid & 31;
    int gid = lane >> 2;
    int tig = lane & 3;
    int w16 = warp * 16;
    int l15 = lane & 15;
    int lhi = (lane >> 4) * 16;
    int l7 = lane & 7;
    int r16 = (lane & 16) ? 8 : 0;
    int b8 = (lane & 8) ? 16 : 0;

#pragma unroll
    for (int t = 0; t < 4; t++) {
        int id = tid + t * 256;
        int r = id >> 3, c = id & 7;
        cpa16(sbase + PA0_B + r * ROWB + c * 16, g_o + (size_t)(i0 + r) * DH + c * 8);
    }
#pragma unroll
    for (int t = 0; t < 2; t++) {
        int id = tid + t * 256;
        int r = id >> 3, c = id & 7;
        cpa16(sbase + PB0_B + r * ROWB + c * 16, g_woh + (size_t)(j0 + r) * C_DIM + c * 8);
    }
    CP_COMMIT();

    float acc[8][4];
#pragma unroll
    for (int n = 0; n < 8; n++)
#pragma unroll
        for (int q = 0; q < 4; q++) acc[n][q] = 0.0f;

    for (int kc = 0; kc < 8; kc++) {
        int cur = kc & 1;
        uint32_t Ac = sbase + (cur ? PA1_B : PA0_B);
        uint32_t Bc = sbase + (cur ? PB1_B : PB0_B);
        __syncthreads();
        if (kc + 1 < 8) {
            uint32_t An = sbase + (cur ? PA0_B : PA1_B);
            uint32_t Bn = sbase + (cur ? PB0_B : PB1_B);
            int hn = kc + 1;
            const __half* Agn = g_o + (size_t)hn * N_TOK * DH + (size_t)i0 * DH;
            const __half* Bgn = g_woh + (size_t)j0 * C_DIM + hn * DH;
#pragma unroll
            for (int t = 0; t < 4; t++) {
                int id = tid + t * 256;
                int r = id >> 3, c = id & 7;
                cpa16(An + r * ROWB + c * 16, Agn + (size_t)r * DH + c * 8);
            }
#pragma unroll
            for (int t = 0; t < 2; t++) {
                int id = tid + t * 256;
                int r = id >> 3, c = id & 7;
                cpa16(Bn + r * ROWB + c * 16, Bgn + (size_t)r * C_DIM + c * 8);
            }
            CP_COMMIT();
            CP_WAIT(1);
        } else {
            CP_WAIT(0);
        }
        __syncthreads();

#pragma unroll
        for (int k = 0; k < 4; k++) {
            uint32_t a[4];
            ldsm4(a, Ac + (w16 + l15) * ROWB + k * 32 + lhi);
#pragma unroll
            for (int np = 0; np < 4; np++) {
                uint32_t b[4];
                ldsm4(b, Bc + (np * 16 + r16 + l7) * ROWB + k * 32 + b8);
                mma16(acc[2 * np], a, b[0], b[1]);
                mma16(acc[2 * np + 1], a, b[2], b[3]);
            }
        }
    }

#pragma unroll
    for (int n = 0; n < 8; n++) {
        int col = n * 8 + 2 * tig;
        float2 bb = *(const float2*)&bo[j0 + col];
        int r0 = i0 + w16 + gid;
        float2 w0;
        w0.x = acc[n][0] + bb.x;
        w0.y = acc[n][1] + bb.y;
        *(float2*)&out[(size_t)r0 * C_DIM + j0 + col] = w0;
        float2 w1;
        w1.x = acc[n][2] + bb.x;
        w1.y = acc[n][3] + bb.y;
        *(float2*)&out[(size_t)(r0 + 8) * C_DIM + j0 + col] = w1;
    }
}

// ---------------- launch ----------------
extern "C" void kernel_launch(void* const* d_in, const int* in_sizes, int n_in,
                              void* d_out, int out_size) {
    (void)in_sizes; (void)n_in; (void)out_size;
    const float* x     = (const float*)d_in[0];
    const float* lat   = (const float*)d_in[1];
    const float* lon   = (const float*)d_in[2];
    const float* w_qkv = (const float*)d_in[3];
    const float* b_qkv = (const float*)d_in[4];
    const float* w_out = (const float*)d_in[5];
    const float* b_out = (const float*)d_in[6];
    float* out = (float*)d_out;

    trig_kernel<<<N_TOK / 256, 256>>>(lat, lon);
    cvt_kernel<<<3072, 256>>>(x, w_qkv, w_out);
    dist_kernel2<<<(NTILE * (NTILE + 1)) / 2, 256>>>();
    finalize_kernel<<<1, 1>>>();

    cudaFuncSetAttribute(qkv_gemm_h, cudaFuncAttributeMaxDynamicSharedMemorySize, PROJ_SMEM_BYTES);
    qkv_gemm_h<<<dim3(3 * C_DIM / 64, N_TOK / 128), 256, PROJ_SMEM_BYTES>>>(b_qkv);

    cudaFuncSetAttribute(attn_mma, cudaFuncAttributeMaxDynamicSharedMemorySize, ATTN_SMEM_BYTES);
    attn_mma<<<dim3(N_TOK / 128, NH), 256, ATTN_SMEM_BYTES>>>();

    cudaFuncSetAttribute(out_gemm_h, cudaFuncAttributeMaxDynamicSharedMemorySize, PROJ_SMEM_BYTES);
    out_gemm_h<<<dim3(C_DIM / 64, N_TOK / 128), 256, PROJ_SMEM_BYTES>>>(b_out, out);
}